// round 3
// baseline (speedup 1.0000x reference)
#include <cuda_runtime.h>
#include <math.h>

#define NROWS 500000
#define NA 5
#define TT 8
#define NE 18
#define MB 4
#define EPSV 1e-8f
#define ML2 (0.02f * 0.02f)
#define BLK 128

__global__ void zero_out_kernel(float* out) { out[0] = 0.0f; }

__global__ void __launch_bounds__(BLK) loss_kernel(
    const float* __restrict__ x,
    const float* __restrict__ yt,
    const float* __restrict__ yp,
    const float* __restrict__ mk,
    const int* __restrict__ trip,
    const int* __restrict__ tvalid,
    float* __restrict__ out)
{
    __shared__ int   s_trip[NE * MB * TT * 3];   // 1728 ints
    __shared__ int   s_valid[NE * MB * TT];      // 576 ints
    __shared__ float st[BLK * 15];
    __shared__ float sp[BLK * 15];
    __shared__ float sm[BLK * 15];

    const int tid = threadIdx.x;

    // stage the small tables (fully cached; cheap)
    for (int i = tid; i < NE * MB * TT * 3; i += BLK) s_trip[i] = trip[i];
    for (int i = tid; i < NE * MB * TT;     i += BLK) s_valid[i] = tvalid[i];

    const int row0 = blockIdx.x * BLK;
    const int cnt  = min(BLK, NROWS - row0);
    const int tot  = cnt * 15;

    if (cnt == BLK) {
        // full block: 1920 floats = 480 float4 per array, 16B-aligned
        const float4* gt4 = (const float4*)(yt + (size_t)row0 * 15);
        const float4* gp4 = (const float4*)(yp + (size_t)row0 * 15);
        const float4* gm4 = (const float4*)(mk + (size_t)row0 * 15);
        float4* st4 = (float4*)st;
        float4* sp4 = (float4*)sp;
        float4* sm4 = (float4*)sm;
#pragma unroll
        for (int i = 0; i < (BLK * 15) / 4 / BLK + 1; i++) {
            int idx = tid + i * BLK;
            if (idx < (BLK * 15) / 4) {
                st4[idx] = gt4[idx];
                sp4[idx] = gp4[idx];
                sm4[idx] = gm4[idx];
            }
        }
    } else {
        const float* gt = yt + (size_t)row0 * 15;
        const float* gp = yp + (size_t)row0 * 15;
        const float* gm = mk + (size_t)row0 * 15;
        for (int i = tid; i < tot; i += BLK) {
            st[i] = gt[i];
            sp[i] = gp[i];
            sm[i] = gm[i];
        }
    }
    __syncthreads();

    float acc = 0.0f;

    if (tid < cnt) {
        const float* t = st + tid * 15;   // stride 15: conflict-free (gcd(15,32)=1)
        const float* p = sp + tid * 15;
        const float* m = sm + tid * 15;

        // ---------------- atom MSE (per-row term) ----------------
        float num = 0.0f, den = 0.0f;
        int avmask = 0;
#pragma unroll
        for (int a = 0; a < NA; a++) {
            float m0 = m[a * 3 + 0], m1 = m[a * 3 + 1], m2 = m[a * 3 + 2];
            float d0 = t[a * 3 + 0] - p[a * 3 + 0];
            float d1 = t[a * 3 + 1] - p[a * 3 + 1];
            float d2 = t[a * 3 + 2] - p[a * 3 + 2];
            float se = d0 * d0 * m0 + d1 * d1 * m1 + d2 * d2 * m2;
            bool v = (m0 > 0.0f) || (m1 > 0.0f) || (m2 > 0.0f);
            if (v) { num += se; den += 1.0f; avmask |= (1 << a); }
        }
        float atom = num / (den + EPSV);

        // ---------------- angle loss (per-row term) ----------------
        const int row = row0 + tid;
        // (row*38+36)*4 bytes = 8*(19*row+18): 8B-aligned -> single LDG.64
        const float2 xg = *(const float2*)(x + (size_t)row * 38 + 36);
        float bd = xg.x, gate = xg.y;
        if (!isfinite(gate)) gate = 0.0f;
        int rid = (int)rintf(gate) - 1;
        rid = min(max(rid, 0), NE - 1);
        if (!isfinite(bd)) bd = 0.0f;
        int bid = min(max((int)rintf(bd), 0), MB - 1);

        const int base = (rid * MB + bid) * TT;

        float anum = 0.0f, aden = 0.0f;
        for (int q = 0; q < TT; q++) {
            const int o = (base + q) * 3;
            const int i0 = s_trip[o + 0];
            const int i1 = s_trip[o + 1];
            const int i2 = s_trip[o + 2];
            bool ok = (i0 >= 0) && (i1 >= 0) && (i2 >= 0) && (s_valid[base + q] > 0);
            const int ii = max(i0, 0), jj = max(i1, 0), kk = max(i2, 0);
            ok = ok && ((avmask >> ii) & 1) && ((avmask >> jj) & 1) && ((avmask >> kk) & 1);

            // true vectors
            float tjx = t[jj * 3 + 0], tjy = t[jj * 3 + 1], tjz = t[jj * 3 + 2];
            float v1tx = t[ii * 3 + 0] - tjx, v1ty = t[ii * 3 + 1] - tjy, v1tz = t[ii * 3 + 2] - tjz;
            float v2tx = t[kk * 3 + 0] - tjx, v2ty = t[kk * 3 + 1] - tjy, v2tz = t[kk * 3 + 2] - tjz;
            // pred vectors
            float pjx = p[jj * 3 + 0], pjy = p[jj * 3 + 1], pjz = p[jj * 3 + 2];
            float v1px = p[ii * 3 + 0] - pjx, v1py = p[ii * 3 + 1] - pjy, v1pz = p[ii * 3 + 2] - pjz;
            float v2px = p[kk * 3 + 0] - pjx, v2py = p[kk * 3 + 1] - pjy, v2pz = p[kk * 3 + 2] - pjz;

            float l1t2 = v1tx * v1tx + v1ty * v1ty + v1tz * v1tz;
            float l2t2 = v2tx * v2tx + v2ty * v2ty + v2tz * v2tz;
            float l1p2 = v1px * v1px + v1py * v1py + v1pz * v1pz;
            float l2p2 = v2px * v2px + v2py * v2py + v2pz * v2pz;

            ok = ok && (l1t2 > ML2) && (l2t2 > ML2) && (l1p2 > ML2) && (l2p2 > ML2);

            float r1t = rsqrtf(fmaxf(l1t2, ML2));
            float r2t = rsqrtf(fmaxf(l2t2, ML2));
            float r1p = rsqrtf(fmaxf(l1p2, ML2));
            float r2p = rsqrtf(fmaxf(l2p2, ML2));

            float u1tx = v1tx * r1t, u1ty = v1ty * r1t, u1tz = v1tz * r1t;
            float u2tx = v2tx * r2t, u2ty = v2ty * r2t, u2tz = v2tz * r2t;
            float u1px = v1px * r1p, u1py = v1py * r1p, u1pz = v1pz * r1p;
            float u2px = v2px * r2p, u2py = v2py * r2p, u2pz = v2pz * r2p;

            float cost = u1tx * u2tx + u1ty * u2ty + u1tz * u2tz;
            float cosp = u1px * u2px + u1py * u2py + u1pz * u2pz;
            const float lo = -1.0f + 1e-6f, hi = 1.0f - 1e-6f;
            cost = fminf(fmaxf(cost, lo), hi);
            cosp = fminf(fmaxf(cosp, lo), hi);

            // cross products (on unit vectors), then norm
            float ctx = u1ty * u2tz - u1tz * u2ty;
            float cty = u1tz * u2tx - u1tx * u2tz;
            float ctz = u1tx * u2ty - u1ty * u2tx;
            float cpx = u1py * u2pz - u1pz * u2py;
            float cpy = u1pz * u2px - u1px * u2pz;
            float cpz = u1px * u2py - u1py * u2px;
            float sint = sqrtf(ctx * ctx + cty * cty + ctz * ctz);
            float sinp = sqrtf(cpx * cpx + cpy * cpy + cpz * cpz);

            float dc = cosp - cost;
            float ds = sinp - sint;
            float per = dc * dc + ds * ds;
            if (ok) { anum += per; aden += 1.0f; }
        }
        float ang = anum / (aden + EPSV);

        acc = atom + ang;
    }

    // ---------------- block reduction ----------------
#pragma unroll
    for (int off = 16; off > 0; off >>= 1)
        acc += __shfl_down_sync(0xffffffffu, acc, off);

    __shared__ float warpsum[BLK / 32];
    if ((tid & 31) == 0) warpsum[tid >> 5] = acc;
    __syncthreads();
    if (tid == 0) {
        float s = 0.0f;
#pragma unroll
        for (int w = 0; w < BLK / 32; w++) s += warpsum[w];
        atomicAdd(out, s * (1.0f / (float)NROWS));
    }
}

extern "C" void kernel_launch(void* const* d_in, const int* in_sizes, int n_in,
                              void* d_out, int out_size)
{
    const float* x      = (const float*)d_in[0];
    const float* yt     = (const float*)d_in[1];
    const float* yp     = (const float*)d_in[2];
    const float* mk     = (const float*)d_in[3];
    const int*   trip   = (const int*)d_in[4];
    const int*   tvalid = (const int*)d_in[5];
    float* out = (float*)d_out;

    zero_out_kernel<<<1, 1>>>(out);
    const int grid = (NROWS + BLK - 1) / BLK;
    loss_kernel<<<grid, BLK>>>(x, yt, yp, mk, trip, tvalid, out);
}

// round 5
// speedup vs baseline: 1.4169x; 1.4169x over previous
#include <cuda_runtime.h>
#include <math.h>

#define NROWS 500000
#define NA 5
#define TT 8
#define NE 18
#define MB 4
#define EPSV 1e-8f
#define ML2 (0.02f * 0.02f)
#define BLK 128
#define NCLS (NE * MB * TT)   // 576

__global__ void zero_out_kernel(float* out) { out[0] = 0.0f; }

__device__ __forceinline__ float sqrt_approx(float a) {
    float r; asm("sqrt.approx.f32 %0, %1;" : "=f"(r) : "f"(a)); return r;
}
__device__ __forceinline__ float rcp_approx(float a) {
    float r; asm("rcp.approx.f32 %0, %1;" : "=f"(r) : "f"(a)); return r;
}

__global__ void __launch_bounds__(BLK, 8) loss_kernel(
    const float* __restrict__ x,
    const float* __restrict__ yt,
    const float* __restrict__ yp,
    const float* __restrict__ mk,
    const int* __restrict__ trip,
    const int* __restrict__ tvalid,
    float* __restrict__ out)
{
    __shared__ unsigned s_pk[NCLS];          // packed (ii,jj,kk,ok) per entry: 2.3 KB
    __shared__ float st[BLK * 15];
    __shared__ float sp[BLK * 15];
    __shared__ float sm[BLK * 15];
    __shared__ float warpsum[BLK / 32];

    const int tid = threadIdx.x;

    // Pack tables: indices in [-1,4] -> clamp to [0,4] (4 bits each), validity 1 bit.
    for (int e = tid; e < NCLS; e += BLK) {
        const int i0 = trip[3 * e + 0];
        const int i1 = trip[3 * e + 1];
        const int i2 = trip[3 * e + 2];
        const int v  = tvalid[e];
        const unsigned ok = (i0 >= 0 && i1 >= 0 && i2 >= 0 && v > 0) ? 1u : 0u;
        const unsigned ii = (unsigned)max(i0, 0);
        const unsigned jj = (unsigned)max(i1, 0);
        const unsigned kk = (unsigned)max(i2, 0);
        s_pk[e] = ii | (jj << 4) | (kk << 8) | (ok << 12);
    }

    const int row0 = blockIdx.x * BLK;
    const int cnt  = min(BLK, NROWS - row0);

    if (cnt == BLK) {
        // full block: 1920 floats = 480 float4 per array, 16B-aligned
        const float4* gt4 = (const float4*)(yt + (size_t)row0 * 15);
        const float4* gp4 = (const float4*)(yp + (size_t)row0 * 15);
        const float4* gm4 = (const float4*)(mk + (size_t)row0 * 15);
        float4* st4 = (float4*)st;
        float4* sp4 = (float4*)sp;
        float4* sm4 = (float4*)sm;
#pragma unroll
        for (int i = 0; i < 4; i++) {
            int idx = tid + i * BLK;
            if (idx < (BLK * 15) / 4) {
                st4[idx] = gt4[idx];
                sp4[idx] = gp4[idx];
                sm4[idx] = gm4[idx];
            }
        }
    } else {
        const int tot = cnt * 15;
        const float* gt = yt + (size_t)row0 * 15;
        const float* gp = yp + (size_t)row0 * 15;
        const float* gm = mk + (size_t)row0 * 15;
        for (int i = tid; i < tot; i += BLK) {
            st[i] = gt[i];
            sp[i] = gp[i];
            sm[i] = gm[i];
        }
    }
    __syncthreads();

    float acc = 0.0f;

    if (tid < cnt) {
        const float* t = st + tid * 15;   // stride 15: conflict-free (gcd(15,32)=1)
        const float* p = sp + tid * 15;
        const float* m = sm + tid * 15;

        // ---------------- atom MSE ----------------
        float num = 0.0f, den = 0.0f;
        unsigned avmask = 0;
#pragma unroll
        for (int a = 0; a < NA; a++) {
            float m0 = m[a * 3 + 0], m1 = m[a * 3 + 1], m2 = m[a * 3 + 2];
            float d0 = t[a * 3 + 0] - p[a * 3 + 0];
            float d1 = t[a * 3 + 1] - p[a * 3 + 1];
            float d2 = t[a * 3 + 2] - p[a * 3 + 2];
            float se = d0 * d0 * m0 + d1 * d1 * m1 + d2 * d2 * m2;
            bool v = (m0 > 0.0f) || (m1 > 0.0f) || (m2 > 0.0f);
            if (v) { num += se; den += 1.0f; avmask |= (1u << a); }
        }
        float atom = num * rcp_approx(den + EPSV);

        // ---------------- angle loss ----------------
        const int row = row0 + tid;
        // (row*38+36)*4 bytes = 8*(19*row+18): 8B-aligned -> single LDG.64
        const float2 xg = *(const float2*)(x + (size_t)row * 38 + 36);
        float bd = xg.x, gate = xg.y;
        if (!isfinite(gate)) gate = 0.0f;
        int rid = (int)rintf(gate) - 1;
        rid = min(max(rid, 0), NE - 1);
        if (!isfinite(bd)) bd = 0.0f;
        int bid = min(max((int)rintf(bd), 0), MB - 1);

        const int base = (rid * MB + bid) * TT;

        float anum = 0.0f, aden = 0.0f;
#pragma unroll 2
        for (int q = 0; q < TT; q++) {
            const unsigned pk = s_pk[base + q];
            const int ii = pk & 15;
            const int jj = (pk >> 4) & 15;
            const int kk = (pk >> 8) & 15;
            unsigned okb = (pk >> 12) & 1u;
            okb &= (avmask >> ii) & (avmask >> jj) & (avmask >> kk) & 1u;

            // true vectors
            float tjx = t[jj * 3 + 0], tjy = t[jj * 3 + 1], tjz = t[jj * 3 + 2];
            float v1tx = t[ii * 3 + 0] - tjx, v1ty = t[ii * 3 + 1] - tjy, v1tz = t[ii * 3 + 2] - tjz;
            float v2tx = t[kk * 3 + 0] - tjx, v2ty = t[kk * 3 + 1] - tjy, v2tz = t[kk * 3 + 2] - tjz;
            // pred vectors
            float pjx = p[jj * 3 + 0], pjy = p[jj * 3 + 1], pjz = p[jj * 3 + 2];
            float v1px = p[ii * 3 + 0] - pjx, v1py = p[ii * 3 + 1] - pjy, v1pz = p[ii * 3 + 2] - pjz;
            float v2px = p[kk * 3 + 0] - pjx, v2py = p[kk * 3 + 1] - pjy, v2pz = p[kk * 3 + 2] - pjz;

            float l1t2 = v1tx * v1tx + v1ty * v1ty + v1tz * v1tz;
            float l2t2 = v2tx * v2tx + v2ty * v2ty + v2tz * v2tz;
            float l1p2 = v1px * v1px + v1py * v1py + v1pz * v1pz;
            float l2p2 = v2px * v2px + v2py * v2py + v2pz * v2pz;

            bool ok = okb && (l1t2 > ML2) && (l2t2 > ML2) && (l1p2 > ML2) && (l2p2 > ML2);

            float r1t = rsqrtf(fmaxf(l1t2, ML2));
            float r2t = rsqrtf(fmaxf(l2t2, ML2));
            float r1p = rsqrtf(fmaxf(l1p2, ML2));
            float r2p = rsqrtf(fmaxf(l2p2, ML2));

            float u1tx = v1tx * r1t, u1ty = v1ty * r1t, u1tz = v1tz * r1t;
            float u2tx = v2tx * r2t, u2ty = v2ty * r2t, u2tz = v2tz * r2t;
            float u1px = v1px * r1p, u1py = v1py * r1p, u1pz = v1pz * r1p;
            float u2px = v2px * r2p, u2py = v2py * r2p, u2pz = v2pz * r2p;

            float cost = u1tx * u2tx + u1ty * u2ty + u1tz * u2tz;
            float cosp = u1px * u2px + u1py * u2py + u1pz * u2pz;
            const float lo = -1.0f + 1e-6f, hi = 1.0f - 1e-6f;
            cost = fminf(fmaxf(cost, lo), hi);
            cosp = fminf(fmaxf(cosp, lo), hi);

            float ctx = u1ty * u2tz - u1tz * u2ty;
            float cty = u1tz * u2tx - u1tx * u2tz;
            float ctz = u1tx * u2ty - u1ty * u2tx;
            float cpx = u1py * u2pz - u1pz * u2py;
            float cpy = u1pz * u2px - u1px * u2pz;
            float cpz = u1px * u2py - u1py * u2px;
            float sint = sqrt_approx(ctx * ctx + cty * cty + ctz * ctz);
            float sinp = sqrt_approx(cpx * cpx + cpy * cpy + cpz * cpz);

            float dc = cosp - cost;
            float ds = sinp - sint;
            float per = dc * dc + ds * ds;
            if (ok) { anum += per; aden += 1.0f; }
        }
        float ang = anum * rcp_approx(aden + EPSV);

        acc = atom + ang;
    }

    // ---------------- block reduction ----------------
#pragma unroll
    for (int off = 16; off > 0; off >>= 1)
        acc += __shfl_down_sync(0xffffffffu, acc, off);

    if ((tid & 31) == 0) warpsum[tid >> 5] = acc;
    __syncthreads();
    if (tid == 0) {
        float s = 0.0f;
#pragma unroll
        for (int w = 0; w < BLK / 32; w++) s += warpsum[w];
        atomicAdd(out, s * (1.0f / (float)NROWS));
    }
}

extern "C" void kernel_launch(void* const* d_in, const int* in_sizes, int n_in,
                              void* d_out, int out_size)
{
    const float* x      = (const float*)d_in[0];
    const float* yt     = (const float*)d_in[1];
    const float* yp     = (const float*)d_in[2];
    const float* mk     = (const float*)d_in[3];
    const int*   trip   = (const int*)d_in[4];
    const int*   tvalid = (const int*)d_in[5];
    float* out = (float*)d_out;

    zero_out_kernel<<<1, 1>>>(out);
    const int grid = (NROWS + BLK - 1) / BLK;
    loss_kernel<<<grid, BLK>>>(x, yt, yp, mk, trip, tvalid, out);
}